// round 13
// baseline (speedup 1.0000x reference)
#include <cuda_runtime.h>
#include <cuda.h>
#include <cuda_bf16.h>
#include <cstdint>

#define NTOK   8192
#define DIM    1024
#define NEXP   8
#define CAP    1024
#define LN_EPS 1e-5f

// Arch-specific feature gate: tcgen05 only exists on sm_100a/sm_103a targets.
#if defined(__CUDA_ARCH_FEAT_SM103_ALL) || defined(__CUDA_ARCH_FEAT_SM100_ALL)
#define HAS_TCGEN05 1
#else
#define HAS_TCGEN05 0
#endif

// ---------------- scratch (device globals: no allocation) -------------------
__device__ float g_h[NTOK * DIM];

// ---------------- PTX helpers (guarded) -------------------------------------
#if HAS_TCGEN05
__device__ __forceinline__ uint32_t smem_u32(const void* p) {
    uint32_t a;
    asm("{ .reg .u64 t; cvta.to.shared.u64 t, %1; cvt.u32.u64 %0, t; }" : "=r"(a) : "l"(p));
    return a;
}
__device__ __forceinline__ uint32_t elect_one_pred() {
    uint32_t p;
    asm volatile("{\n\t.reg .pred p;\n\telect.sync _|p, 0xFFFFFFFF;\n\tselp.b32 %0, 1, 0, p;\n\t}" : "=r"(p));
    return p;
}

#define MBARRIER_INIT(addr, cnt) \
    asm volatile("mbarrier.init.shared.b64 [%0], %1;" :: "r"(addr), "r"(cnt) : "memory")
#define MBARRIER_INVAL(addr) \
    asm volatile("mbarrier.inval.shared.b64 [%0];" :: "r"(addr) : "memory")
#define MBARRIER_EXPECT_TX(addr, bytes) \
    asm volatile("mbarrier.arrive.expect_tx.shared.b64 _, [%0], %1;" :: "r"(addr), "r"(bytes) : "memory")
#define MBARRIER_ARRIVE(addr) \
    asm volatile("mbarrier.arrive.shared.b64 _, [%0];" :: "r"(addr) : "memory")
#define MBARRIER_WAIT_PARITY(addr, par) do {                                        \
    uint32_t _m = (addr), _p = (par), _d;                                           \
    asm volatile("{\n\t.reg .pred p;\n\t"                                           \
        "mbarrier.try_wait.parity.acquire.cta.shared::cta.b64 p, [%1], %2;\n\t"     \
        "selp.b32 %0, 1, 0, p;\n\t}" : "=r"(_d) : "r"(_m), "r"(_p) : "memory");     \
    if (!_d) {                                                                      \
        asm volatile("{\n\t.reg .pred P1;\n\t"                                      \
            "WL_%=:\n\t"                                                            \
            "mbarrier.try_wait.parity.acquire.cta.shared::cta.b64 P1, [%0], %1, 0x989680;\n\t" \
            "@P1 bra.uni WD_%=;\n\tbra.uni WL_%=;\n\tWD_%=:\n\t}"                   \
            :: "r"(_m), "r"(_p) : "memory");                                        \
    } } while (0)

#define TMA_LOAD_2D(smem_addr, map, cx, cy, mbar) \
    asm volatile("cp.async.bulk.tensor.2d.shared::cta.global.tile.mbarrier::complete_tx::bytes " \
        "[%0], [%1, {%2, %3}], [%4];" \
        :: "r"(smem_addr), "l"(map), "r"(cx), "r"(cy), "r"(mbar) : "memory")

#define TCGEN05_ALLOC(smem_addr, ncols) \
    asm volatile("tcgen05.alloc.cta_group::1.sync.aligned.shared::cta.b32 [%0], %1;" \
                 :: "r"(smem_addr), "r"(ncols) : "memory")
#define TCGEN05_DEALLOC(tmem, ncols) \
    asm volatile("tcgen05.dealloc.cta_group::1.sync.aligned.b32 %0, %1;" :: "r"(tmem), "r"(ncols))
#define TCGEN05_RELINQ() \
    asm volatile("tcgen05.relinquish_alloc_permit.cta_group::1.sync.aligned;")
#define TCGEN05_COMMIT(mbar) \
    asm volatile("tcgen05.commit.cta_group::1.mbarrier::arrive::one.shared::cluster.b64 [%0];" \
                 :: "r"(mbar) : "memory")
#define TCGEN05_FENCE_AFTER() \
    asm volatile("tcgen05.fence::after_thread_sync;" ::: "memory")
#define TCGEN05_FENCE_BEFORE() \
    asm volatile("tcgen05.fence::before_thread_sync;" ::: "memory")
#define TCGEN05_WAIT_LD() \
    asm volatile("tcgen05.wait::ld.sync.aligned;" ::: "memory")
#define FENCE_PROXY_ASYNC() \
    asm volatile("fence.proxy.async.shared::cta;" ::: "memory")

#define TCGEN05_LD_X32(r, tmem_addr) \
    asm volatile("tcgen05.ld.sync.aligned.32x32b.x32.b32 " \
        "{%0, %1, %2, %3, %4, %5, %6, %7, %8, %9, %10, %11, %12, %13, %14, %15, " \
        " %16, %17, %18, %19, %20, %21, %22, %23, %24, %25, %26, %27, %28, %29, %30, %31}, [%32];" \
        : "=r"((r)[0]),  "=r"((r)[1]),  "=r"((r)[2]),  "=r"((r)[3]),  \
          "=r"((r)[4]),  "=r"((r)[5]),  "=r"((r)[6]),  "=r"((r)[7]),  \
          "=r"((r)[8]),  "=r"((r)[9]),  "=r"((r)[10]), "=r"((r)[11]), \
          "=r"((r)[12]), "=r"((r)[13]), "=r"((r)[14]), "=r"((r)[15]), \
          "=r"((r)[16]), "=r"((r)[17]), "=r"((r)[18]), "=r"((r)[19]), \
          "=r"((r)[20]), "=r"((r)[21]), "=r"((r)[22]), "=r"((r)[23]), \
          "=r"((r)[24]), "=r"((r)[25]), "=r"((r)[26]), "=r"((r)[27]), \
          "=r"((r)[28]), "=r"((r)[29]), "=r"((r)[30]), "=r"((r)[31]) \
        : "r"(tmem_addr))

// SS-mode tf32 MMA, cta_group::1, fp32 accumulate in TMEM (K=8 per step)
__device__ __forceinline__ void mma_tf32_ss(uint32_t d_tmem, uint64_t a_desc,
                                            uint64_t b_desc, uint32_t idesc, bool acc) {
    uint32_t en = acc ? 1u : 0u, z = 0u;
    asm volatile("{\n\t.reg .pred p;\n\tsetp.ne.u32 p, %5, 0;\n\t"
        "tcgen05.mma.cta_group::1.kind::tf32 [%0], %1, %2, %3, {%4, %4, %4, %4}, p;\n\t}"
        :: "r"(d_tmem), "l"(a_desc), "l"(b_desc), "r"(idesc), "r"(z), "r"(en) : "memory");
}

// SW64 K-major descriptor (layout=4, version=1, SBO=32, LBO=1) — proven R6/R7/R11.
static __device__ __forceinline__ uint64_t make_desc_sw64(uint32_t addr) {
    const uint64_t BASE = (4ull << 61) | (1ull << 46) | (32ull << 32) | (1ull << 16);
    return BASE | ((uint64_t)(addr >> 4) & 0x3FFFull);
}

// idesc: dtype F32 (1<<4), atype TF32 (2<<7), btype TF32 (2<<10), N=256, M=128
#define MMA_IDESC ((1u << 4) | (2u << 7) | (2u << 10) | ((256u / 8) << 17) | ((128u / 16) << 24))
#endif // HAS_TCGEN05

// ---------------------------------------------------------------------------
// GEMM: per expert e, H = relu(X_e @ W_e + b_e), single-pass tf32.
//   Tile M=256 x N=256, K_CHUNK=16, NSTAGE=4. B is loaded RAW ([k][n], no
//   swizzle) via TMA and transposed in-SMEM by the producer warps into the
//   proven K-major SW64 layout. No standalone transpose kernel, no Wt scratch.
// ---------------------------------------------------------------------------
#define NSTAGE      4
#define K_CHUNK     16
#define N_CHUNKS    64               // 1024 / 16
#define STAGE_BYTES 49152            // A 16K | Braw 16K | Bkm 16K
#define ST_A    0
#define ST_BRAW 16384
#define ST_BKM  32768
#define OFF_BIAS  (NSTAGE * STAGE_BYTES)       // 196608, 1KB
#define OFF_TPTR  (OFF_BIAS + 1024)            // 16B
#define OFF_FULLA (OFF_TPTR + 16)              // 4 x 8B
#define OFF_FULLB (OFF_FULLA + 32)             // 4 x 8B
#define OFF_READY (OFF_FULLB + 32)             // 4 x 8B
#define OFF_EMPTY (OFF_READY + 32)             // 4 x 8B
#define OFF_FINAL (OFF_EMPTY + 32)
#define SMEM_SIZE (OFF_FINAL + 16)

__global__ __launch_bounds__(256, 1)
void gemm_tc_kernel(const __grid_constant__ CUtensorMap tmX,
                    const __grid_constant__ CUtensorMap tmWraw,
                    const float* __restrict__ X,
                    const float* __restrict__ W,
                    const float* __restrict__ bias,
                    float* __restrict__ H)
{
#if HAS_TCGEN05
    extern __shared__ __align__(1024) char smem[];
    const uint32_t sbase  = smem_u32(smem);
    const int e      = blockIdx.z;
    const int tile_n = blockIdx.x * 256;
    const int tile_m = blockIdx.y * 256;
    const int tid    = threadIdx.x;
    const int wid    = tid >> 5;
    const int lid    = tid & 31;

    if (wid == 0) {
        TCGEN05_ALLOC(sbase + OFF_TPTR, 512);
        TCGEN05_RELINQ();
    }
    if (tid == 0) {
        #pragma unroll
        for (int s = 0; s < NSTAGE; ++s) {
            MBARRIER_INIT(sbase + OFF_FULLA + s * 8, 1);    // expect_tx by tid0
            MBARRIER_INIT(sbase + OFF_FULLB + s * 8, 1);    // expect_tx by tid0
            MBARRIER_INIT(sbase + OFF_READY + s * 8, 128);  // producer threads
            MBARRIER_INIT(sbase + OFF_EMPTY + s * 8, 1);    // one commit
        }
        MBARRIER_INIT(sbase + OFF_FINAL, 1);
    }
    ((float*)(smem + OFF_BIAS))[tid] = bias[e * DIM + tile_n + tid];
    __syncthreads();
    uint32_t tmem;
    asm volatile("ld.shared.b32 %0, [%1];" : "=r"(tmem) : "r"(sbase + OFF_TPTR));

    if (wid < 4) {
        // ------- producers: TMA issue (tid0) + in-SMEM B transpose (all 128)
        const int rowA = e * CAP + tile_m;            // X rows, 256-row box
        int st = 0, it = 0;
        for (int c = 0; c < N_CHUNKS; ++c) {
            if (c >= NSTAGE)
                MBARRIER_WAIT_PARITY(sbase + OFF_EMPTY + st * 8, (it - 1) & 1);
            const uint32_t bb = sbase + st * STAGE_BYTES;
            if (tid == 0) {
                const int cx = c * K_CHUNK;
                MBARRIER_EXPECT_TX(sbase + OFF_FULLA + st * 8, 16384);
                TMA_LOAD_2D(bb + ST_A, &tmX, cx, rowA, sbase + OFF_FULLA + st * 8);
                MBARRIER_EXPECT_TX(sbase + OFF_FULLB + st * 8, 16384);
                TMA_LOAD_2D(bb + ST_BRAW, &tmWraw, tile_n, e * DIM + cx,
                            sbase + OFF_FULLB + st * 8);
            }
            // wait raw B, transpose [16k][256n] -> K-major SW64 [256n][16k]
            MBARRIER_WAIT_PARITY(sbase + OFF_FULLB + st * 8, it & 1);
            {
                const float* raw = (const float*)(smem + st * STAGE_BYTES + ST_BRAW);
                char*        bkm = smem + st * STAGE_BYTES + ST_BKM;
                #pragma unroll
                for (int rr = 0; rr < 2; ++rr) {
                    const int n = tid * 2 + rr;
                    float v[16];
                    #pragma unroll
                    for (int k = 0; k < 16; ++k)
                        v[k] = raw[k * 256 + n];       // raw row = 1024B = 256 f32
                    #pragma unroll
                    for (int cg = 0; cg < 4; ++cg) {
                        int byte = n * 64 + cg * 16;
                        int sw   = byte ^ ((byte >> 3) & 0x30);   // SW64 swizzle
                        *(float4*)(bkm + sw) = *(float4*)&v[cg * 4];
                    }
                }
            }
            FENCE_PROXY_ASYNC();                       // STS -> async-proxy MMA read
            MBARRIER_ARRIVE(sbase + OFF_READY + st * 8);
            if (++st == NSTAGE) { st = 0; ++it; }
        }
    } else if (wid == 4) {
        // ---------------- MMA warp (single elected thread)
        if (elect_one_pred()) {
            int st = 0, it = 0;
            for (int c = 0; c < N_CHUNKS; ++c) {
                MBARRIER_WAIT_PARITY(sbase + OFF_FULLA + st * 8, it & 1);
                MBARRIER_WAIT_PARITY(sbase + OFF_READY + st * 8, it & 1);
                const uint32_t bb = sbase + st * STAGE_BYTES;
                uint64_t dA = make_desc_sw64(bb + ST_A);
                uint64_t dB = make_desc_sw64(bb + ST_BKM);
                #pragma unroll
                for (int h = 0; h < 2; ++h) {                 // M halves
                    const uint32_t D   = tmem + h * 256;
                    const uint64_t hof = h * 512;             // 128 rows x 64B = 512 units
                    #pragma unroll
                    for (int kk = 0; kk < 2; ++kk) {          // K=8 steps (+2 units = 32B)
                        mma_tf32_ss(D, dA + hof + kk * 2, dB + kk * 2, MMA_IDESC,
                                    !(c == 0 && kk == 0));
                    }
                }
                TCGEN05_COMMIT(sbase + OFF_EMPTY + st * 8);
                if (++st == NSTAGE) { st = 0; ++it; }
            }
            TCGEN05_COMMIT(sbase + OFF_FINAL);
        }
    }

    // ---------------- epilogue: 8 warps (half = wid>>2, sub = wid&3)
    MBARRIER_WAIT_PARITY(sbase + OFF_FINAL, 0);
    TCGEN05_FENCE_AFTER();

    {
        const int half = wid >> 2, sub = wid & 3;
        const int row  = tile_m + half * 128 + sub * 32 + lid;
        float* outp = H + (size_t)(e * CAP + row) * DIM + tile_n;
        const float* bs = (const float*)(smem + OFF_BIAS);
        const uint32_t dbase = tmem + half * 256;
        #pragma unroll
        for (int base = 0; base < 256; base += 32) {
            uint32_t r[32];
            TCGEN05_LD_X32(r, dbase + base);
            TCGEN05_WAIT_LD();
            float v[32];
            #pragma unroll
            for (int i = 0; i < 32; ++i)
                v[i] = fmaxf(__uint_as_float(r[i]) + bs[base + i], 0.f);
            #pragma unroll
            for (int q = 0; q < 8; ++q)
                *(float4*)(outp + base + q * 4) = *(float4*)&v[q * 4];
        }
        TCGEN05_FENCE_BEFORE();
    }
    __syncthreads();
    if (tid == 0) {
        #pragma unroll
        for (int s = 0; s < NSTAGE; ++s) {
            MBARRIER_INVAL(sbase + OFF_FULLA + s * 8);
            MBARRIER_INVAL(sbase + OFF_FULLB + s * 8);
            MBARRIER_INVAL(sbase + OFF_READY + s * 8);
            MBARRIER_INVAL(sbase + OFF_EMPTY + s * 8);
        }
        MBARRIER_INVAL(sbase + OFF_FINAL);
    }
    __syncthreads();
    if (wid == 0) TCGEN05_DEALLOC(tmem, 512);

#else
    // ---------------- trivial correct fallback (family-level image; not used on GB300)
    const int e      = blockIdx.z;
    const int tile_n = blockIdx.x * 256;
    const int tile_m = blockIdx.y * 256;
    const int tid    = threadIdx.x;
    const int row    = tile_m + tid;
    const float* Ap = X + (size_t)(e * CAP + row) * DIM;
    for (int n = 0; n < 256; ++n) {
        const float* Bp = W + (size_t)e * DIM * DIM + tile_n + n;
        float s = 0.f;
        for (int k = 0; k < DIM; ++k) s = fmaf(Ap[k], Bp[(size_t)k * DIM], s);
        s += bias[e * DIM + tile_n + n];
        H[(size_t)(e * CAP + row) * DIM + tile_n + n] = fmaxf(s, 0.f);
    }
#endif
}

// ---------------------------------------------------------------------------
// LayerNorm: 2 rows per 512-thread CTA (256 threads per row).
// ---------------------------------------------------------------------------
__global__ __launch_bounds__(512)
void layernorm_kernel(const float* __restrict__ H,
                      const float* __restrict__ gamma,
                      const float* __restrict__ beta,
                      float* __restrict__ out)
{
    const int tid  = threadIdx.x;
    const int r    = tid >> 8;               // 0..1 row within CTA
    const int rt   = tid & 255;              // thread within row
    const int row  = blockIdx.x * 2 + r;
    const int e    = row >> 10;

    const float* h = H + (size_t)row * DIM;
    float4 v = *(const float4*)(h + rt * 4);

    float s  = v.x + v.y + v.z + v.w;
    float sq = v.x * v.x + v.y * v.y + v.z * v.z + v.w * v.w;

    #pragma unroll
    for (int off = 16; off > 0; off >>= 1) {
        s  += __shfl_xor_sync(0xffffffffu, s,  off);
        sq += __shfl_xor_sync(0xffffffffu, sq, off);
    }

    __shared__ float red_s[16], red_q[16];
    const int wid = tid >> 5, lid = tid & 31;
    if (lid == 0) { red_s[wid] = s; red_q[wid] = sq; }
    __syncthreads();

    float ts = 0.f, tq = 0.f;
    #pragma unroll
    for (int w = 0; w < 8; ++w) {
        ts += red_s[r * 8 + w];
        tq += red_q[r * 8 + w];
    }
    const float mean = ts * (1.f / DIM);
    const float var  = tq * (1.f / DIM) - mean * mean;
    const float rstd = rsqrtf(var + LN_EPS);

    float4 g  = *(const float4*)(gamma + (size_t)e * DIM + rt * 4);
    float4 bt = *(const float4*)(beta  + (size_t)e * DIM + rt * 4);

    float4 o;
    o.x = (v.x - mean) * rstd * g.x + bt.x;
    o.y = (v.y - mean) * rstd * g.y + bt.y;
    o.z = (v.z - mean) * rstd * g.z + bt.z;
    o.w = (v.w - mean) * rstd * g.w + bt.w;
    *(float4*)(out + (size_t)row * DIM + rt * 4) = o;
}

// ---------------------------------------------------------------------------
typedef CUresult (CUDAAPI *pfn_encode_t)(
    CUtensorMap*, CUtensorMapDataType, cuuint32_t, void*,
    const cuuint64_t*, const cuuint64_t*, const cuuint32_t*, const cuuint32_t*,
    CUtensorMapInterleave, CUtensorMapSwizzle, CUtensorMapL2promotion,
    CUtensorMapFloatOOBfill);

extern "C" void kernel_launch(void* const* d_in, const int* in_sizes, int n_in,
                              void* d_out, int out_size)
{
    const float* x     = (const float*)d_in[0];
    // d_in[1] = expert_frequency (equal capacities) — unused
    const float* W     = (const float*)d_in[2];
    const float* bias  = (const float*)d_in[3];
    const float* gamma = (const float*)d_in[4];
    const float* beta  = (const float*)d_in[5];
    float*       out   = (float*)d_out;

    float* h;
    cudaGetSymbolAddress((void**)&h, g_h);

    static bool init_done = false;
    static CUtensorMap tmX, tmWraw;
    static const float* x_cached = nullptr;
    if (!init_done || x_cached != x) {
        cudaFuncSetAttribute(gemm_tc_kernel,
                             cudaFuncAttributeMaxDynamicSharedMemorySize, SMEM_SIZE);
        void* p = nullptr;
        cudaDriverEntryPointQueryResult qr;
        if (cudaGetDriverEntryPointByVersion("cuTensorMapEncodeTiled", &p, 12000,
                                             cudaEnableDefault, &qr) != cudaSuccess || !p) {
            cudaGetDriverEntryPoint("cuTensorMapEncodeTiled", &p, cudaEnableDefault, &qr);
        }
        pfn_encode_t fn = (pfn_encode_t)p;

        // X: [8192 rows][1024 f32], SW64, box 16 x 256 (64B x 256 rows)
        {
            cuuint64_t dims[2]    = {(cuuint64_t)DIM, (cuuint64_t)NTOK};
            cuuint64_t strides[1] = {(cuuint64_t)(DIM * 4)};
            cuuint32_t box[2]     = {16, 256};
            cuuint32_t estr[2]    = {1, 1};
            fn(&tmX, CU_TENSOR_MAP_DATA_TYPE_FLOAT32, 2, (void*)x,
               dims, strides, box, estr,
               CU_TENSOR_MAP_INTERLEAVE_NONE, CU_TENSOR_MAP_SWIZZLE_64B,
               CU_TENSOR_MAP_L2_PROMOTION_L2_128B, CU_TENSOR_MAP_FLOAT_OOB_FILL_NONE);
        }
        // W raw: [8192 rows = e*1024+k][1024 n f32], NO swizzle, box 256 x 16
        {
            cuuint64_t dims[2]    = {(cuuint64_t)DIM, (cuuint64_t)(NEXP * DIM)};
            cuuint64_t strides[1] = {(cuuint64_t)(DIM * 4)};
            cuuint32_t box[2]     = {256, 16};
            cuuint32_t estr[2]    = {1, 1};
            fn(&tmWraw, CU_TENSOR_MAP_DATA_TYPE_FLOAT32, 2, (void*)W,
               dims, strides, box, estr,
               CU_TENSOR_MAP_INTERLEAVE_NONE, CU_TENSOR_MAP_SWIZZLE_NONE,
               CU_TENSOR_MAP_L2_PROMOTION_L2_128B, CU_TENSOR_MAP_FLOAT_OOB_FILL_NONE);
        }
        init_done = true;
        x_cached = x;
    }

    dim3 grid(DIM / 256, CAP / 256, NEXP);  // 4 x 4 x 8 = 128 CTAs, 1 wave
    gemm_tc_kernel<<<grid, 256, SMEM_SIZE>>>(tmX, tmWraw, x, W, bias, h);

    layernorm_kernel<<<NTOK / 2, 512>>>(h, gamma, beta, out);
}

// round 14
// speedup vs baseline: 1.8028x; 1.8028x over previous
#include <cuda_runtime.h>
#include <cuda.h>
#include <cuda_bf16.h>
#include <cstdint>

#define NTOK   8192
#define DIM    1024
#define NEXP   8
#define CAP    1024
#define LN_EPS 1e-5f

// Arch-specific feature gate: tcgen05 only exists on sm_100a/sm_103a targets.
#if defined(__CUDA_ARCH_FEAT_SM103_ALL) || defined(__CUDA_ARCH_FEAT_SM100_ALL)
#define HAS_TCGEN05 1
#else
#define HAS_TCGEN05 0
#endif

// ---------------- scratch (device globals: no allocation) -------------------
__device__ float g_wt[NEXP * DIM * DIM];   // W transposed: [e][n][k], fp32
__device__ float g_h [NTOK * DIM];

// ---------------- PTX helpers (guarded) -------------------------------------
#if HAS_TCGEN05
__device__ __forceinline__ uint32_t smem_u32(const void* p) {
    uint32_t a;
    asm("{ .reg .u64 t; cvta.to.shared.u64 t, %1; cvt.u32.u64 %0, t; }" : "=r"(a) : "l"(p));
    return a;
}
__device__ __forceinline__ uint32_t elect_one_pred() {
    uint32_t p;
    asm volatile("{\n\t.reg .pred p;\n\telect.sync _|p, 0xFFFFFFFF;\n\tselp.b32 %0, 1, 0, p;\n\t}" : "=r"(p));
    return p;
}

#define MBARRIER_INIT(addr, cnt) \
    asm volatile("mbarrier.init.shared.b64 [%0], %1;" :: "r"(addr), "r"(cnt) : "memory")
#define MBARRIER_INVAL(addr) \
    asm volatile("mbarrier.inval.shared.b64 [%0];" :: "r"(addr) : "memory")
#define MBARRIER_EXPECT_TX(addr, bytes) \
    asm volatile("mbarrier.arrive.expect_tx.shared.b64 _, [%0], %1;" :: "r"(addr), "r"(bytes) : "memory")
#define MBARRIER_WAIT_PARITY(addr, par) do {                                        \
    uint32_t _m = (addr), _p = (par), _d;                                           \
    asm volatile("{\n\t.reg .pred p;\n\t"                                           \
        "mbarrier.try_wait.parity.acquire.cta.shared::cta.b64 p, [%1], %2;\n\t"     \
        "selp.b32 %0, 1, 0, p;\n\t}" : "=r"(_d) : "r"(_m), "r"(_p) : "memory");     \
    if (!_d) {                                                                      \
        asm volatile("{\n\t.reg .pred P1;\n\t"                                      \
            "WL_%=:\n\t"                                                            \
            "mbarrier.try_wait.parity.acquire.cta.shared::cta.b64 P1, [%0], %1, 0x989680;\n\t" \
            "@P1 bra.uni WD_%=;\n\tbra.uni WL_%=;\n\tWD_%=:\n\t}"                   \
            :: "r"(_m), "r"(_p) : "memory");                                        \
    } } while (0)

#define TMA_LOAD_2D(smem_addr, map, cx, cy, mbar) \
    asm volatile("cp.async.bulk.tensor.2d.shared::cta.global.tile.mbarrier::complete_tx::bytes " \
        "[%0], [%1, {%2, %3}], [%4];" \
        :: "r"(smem_addr), "l"(map), "r"(cx), "r"(cy), "r"(mbar) : "memory")

#define TCGEN05_ALLOC(smem_addr, ncols) \
    asm volatile("tcgen05.alloc.cta_group::1.sync.aligned.shared::cta.b32 [%0], %1;" \
                 :: "r"(smem_addr), "r"(ncols) : "memory")
#define TCGEN05_DEALLOC(tmem, ncols) \
    asm volatile("tcgen05.dealloc.cta_group::1.sync.aligned.b32 %0, %1;" :: "r"(tmem), "r"(ncols))
#define TCGEN05_RELINQ() \
    asm volatile("tcgen05.relinquish_alloc_permit.cta_group::1.sync.aligned;")
#define TCGEN05_COMMIT(mbar) \
    asm volatile("tcgen05.commit.cta_group::1.mbarrier::arrive::one.shared::cluster.b64 [%0];" \
                 :: "r"(mbar) : "memory")
#define TCGEN05_FENCE_AFTER() \
    asm volatile("tcgen05.fence::after_thread_sync;" ::: "memory")
#define TCGEN05_FENCE_BEFORE() \
    asm volatile("tcgen05.fence::before_thread_sync;" ::: "memory")
#define TCGEN05_WAIT_LD() \
    asm volatile("tcgen05.wait::ld.sync.aligned;" ::: "memory")

#define TCGEN05_LD_X32(r, tmem_addr) \
    asm volatile("tcgen05.ld.sync.aligned.32x32b.x32.b32 " \
        "{%0, %1, %2, %3, %4, %5, %6, %7, %8, %9, %10, %11, %12, %13, %14, %15, " \
        " %16, %17, %18, %19, %20, %21, %22, %23, %24, %25, %26, %27, %28, %29, %30, %31}, [%32];" \
        : "=r"((r)[0]),  "=r"((r)[1]),  "=r"((r)[2]),  "=r"((r)[3]),  \
          "=r"((r)[4]),  "=r"((r)[5]),  "=r"((r)[6]),  "=r"((r)[7]),  \
          "=r"((r)[8]),  "=r"((r)[9]),  "=r"((r)[10]), "=r"((r)[11]), \
          "=r"((r)[12]), "=r"((r)[13]), "=r"((r)[14]), "=r"((r)[15]), \
          "=r"((r)[16]), "=r"((r)[17]), "=r"((r)[18]), "=r"((r)[19]), \
          "=r"((r)[20]), "=r"((r)[21]), "=r"((r)[22]), "=r"((r)[23]), \
          "=r"((r)[24]), "=r"((r)[25]), "=r"((r)[26]), "=r"((r)[27]), \
          "=r"((r)[28]), "=r"((r)[29]), "=r"((r)[30]), "=r"((r)[31]) \
        : "r"(tmem_addr))

// SS-mode tf32 MMA, cta_group::1, fp32 accumulate in TMEM (K=8 per step)
__device__ __forceinline__ void mma_tf32_ss(uint32_t d_tmem, uint64_t a_desc,
                                            uint64_t b_desc, uint32_t idesc, bool acc) {
    uint32_t en = acc ? 1u : 0u, z = 0u;
    asm volatile("{\n\t.reg .pred p;\n\tsetp.ne.u32 p, %5, 0;\n\t"
        "tcgen05.mma.cta_group::1.kind::tf32 [%0], %1, %2, %3, {%4, %4, %4, %4}, p;\n\t}"
        :: "r"(d_tmem), "l"(a_desc), "l"(b_desc), "r"(idesc), "r"(z), "r"(en) : "memory");
}

// SW64 K-major descriptor (layout=4, version=1, SBO=32, LBO=1) — proven R6/R7/R11.
static __device__ __forceinline__ uint64_t make_desc_sw64(uint32_t addr) {
    const uint64_t BASE = (4ull << 61) | (1ull << 46) | (32ull << 32) | (1ull << 16);
    return BASE | ((uint64_t)(addr >> 4) & 0x3FFFull);
}

// idesc: dtype F32 (1<<4), atype TF32 (2<<7), btype TF32 (2<<10), N=256, M=128
#define MMA_IDESC ((1u << 4) | (2u << 7) | (2u << 10) | ((256u / 8) << 17) | ((128u / 16) << 24))
#endif // HAS_TCGEN05

// ---------------------------------------------------------------------------
// W transpose (fp32): 2 x (64x64) tiles per CTA along k, all 8 LDG.128 issued
// up-front (MLP 8). Bank-clean pad-65 layout (verified conflict-free gather).
// grid = (16 n-tiles, 8 k-pairs, 8 experts) = 1024 CTAs.
// ---------------------------------------------------------------------------
__global__ __launch_bounds__(256)
void transpose_w_kernel(const float* __restrict__ W, float* __restrict__ Wt)
{
    __shared__ float t0[64][65];
    __shared__ float t1[64][65];
    const int e  = blockIdx.z;
    const int k0 = blockIdx.y * 128;
    const int n0 = blockIdx.x * 64;
    const int tid = threadIdx.x;
    const int rr  = tid >> 4;           // 0..15 (row group)
    const int c4  = tid & 15;           // 0..15 float4 group

    const float* Wp = W + (size_t)e * DIM * DIM;
    float4 a0[4], a1[4];
    #pragma unroll
    for (int i = 0; i < 4; ++i) {
        int row = rr + i * 16;
        a0[i] = *(const float4*)(Wp + (size_t)(k0 + row) * DIM + n0 + c4 * 4);
        a1[i] = *(const float4*)(Wp + (size_t)(k0 + 64 + row) * DIM + n0 + c4 * 4);
    }
    #pragma unroll
    for (int i = 0; i < 4; ++i) {
        int row = rr + i * 16;
        t0[row][c4 * 4 + 0] = a0[i].x; t0[row][c4 * 4 + 1] = a0[i].y;
        t0[row][c4 * 4 + 2] = a0[i].z; t0[row][c4 * 4 + 3] = a0[i].w;
        t1[row][c4 * 4 + 0] = a1[i].x; t1[row][c4 * 4 + 1] = a1[i].y;
        t1[row][c4 * 4 + 2] = a1[i].z; t1[row][c4 * 4 + 3] = a1[i].w;
    }
    __syncthreads();

    float* Wtp = Wt + (size_t)e * DIM * DIM;
    #pragma unroll
    for (int i = 0; i < 4; ++i) {
        int n = rr + i * 16;
        float4 v0, v1;
        v0.x = t0[c4 * 4 + 0][n]; v0.y = t0[c4 * 4 + 1][n];
        v0.z = t0[c4 * 4 + 2][n]; v0.w = t0[c4 * 4 + 3][n];
        v1.x = t1[c4 * 4 + 0][n]; v1.y = t1[c4 * 4 + 1][n];
        v1.z = t1[c4 * 4 + 2][n]; v1.w = t1[c4 * 4 + 3][n];
        *(float4*)(Wtp + (size_t)(n0 + n) * DIM + k0      + c4 * 4) = v0;
        *(float4*)(Wtp + (size_t)(n0 + n) * DIM + k0 + 64 + c4 * 4) = v1;
    }
}

// ---------------------------------------------------------------------------
// GEMM (R11, best measured): single-pass tf32, tile M=256 x N=256,
// K_CHUNK=16 (SW64), NSTAGE=6, TMA producer, 128 CTAs = 1 wave.
// ---------------------------------------------------------------------------
#define NSTAGE      6
#define K_CHUNK     16
#define N_CHUNKS    64               // 1024 / 16
#define STAGE_BYTES 32768            // A 16K (256r x 64B) + B 16K (256r x 64B)
#define ST_A 0
#define ST_B 16384
#define OFF_BIAS  (NSTAGE * STAGE_BYTES)       // 196608, 1KB
#define OFF_TPTR  (OFF_BIAS + 1024)
#define OFF_FULL  (OFF_TPTR + 16)              // 6 x 8B
#define OFF_EMPTY (OFF_FULL + 48)              // 6 x 8B
#define OFF_FINAL (OFF_EMPTY + 48)
#define SMEM_SIZE (OFF_FINAL + 16)

__global__ __launch_bounds__(256, 1)
void gemm_tc_kernel(const __grid_constant__ CUtensorMap tmX,
                    const __grid_constant__ CUtensorMap tmW,
                    const float* __restrict__ X,
                    const float* __restrict__ Wt,
                    const float* __restrict__ bias,
                    float* __restrict__ H)
{
#if HAS_TCGEN05
    extern __shared__ __align__(1024) char smem[];
    const uint32_t sbase  = smem_u32(smem);
    const int e      = blockIdx.z;
    const int tile_n = blockIdx.x * 256;
    const int tile_m = blockIdx.y * 256;
    const int tid    = threadIdx.x;
    const int wid    = tid >> 5;
    const int lid    = tid & 31;

    if (wid == 0) {
        TCGEN05_ALLOC(sbase + OFF_TPTR, 512);
        TCGEN05_RELINQ();
    }
    if (tid == 0) {
        #pragma unroll
        for (int s = 0; s < NSTAGE; ++s) {
            MBARRIER_INIT(sbase + OFF_FULL  + s * 8, 1);   // expect_tx by tid0
            MBARRIER_INIT(sbase + OFF_EMPTY + s * 8, 1);   // one commit
        }
        MBARRIER_INIT(sbase + OFF_FINAL, 1);
    }
    ((float*)(smem + OFF_BIAS))[tid] = bias[e * DIM + tile_n + tid];
    __syncthreads();
    uint32_t tmem;
    asm volatile("ld.shared.b32 %0, [%1];" : "=r"(tmem) : "r"(sbase + OFF_TPTR));

    if (tid == 0) {
        // ------- producer: 2 TMA issues per chunk (A 256 rows, B 256 rows)
        const int rowA = e * CAP + tile_m;
        const int rowB = e * DIM + tile_n;
        int st = 0, it = 0;
        for (int c = 0; c < N_CHUNKS; ++c) {
            if (c >= NSTAGE)
                MBARRIER_WAIT_PARITY(sbase + OFF_EMPTY + st * 8, (it - 1) & 1);
            const uint32_t bb = sbase + st * STAGE_BYTES;
            const uint32_t fb = sbase + OFF_FULL + st * 8;
            const int cx = c * K_CHUNK;
            MBARRIER_EXPECT_TX(fb, STAGE_BYTES);
            TMA_LOAD_2D(bb + ST_A, &tmX, cx, rowA, fb);
            TMA_LOAD_2D(bb + ST_B, &tmW, cx, rowB, fb);
            if (++st == NSTAGE) { st = 0; ++it; }
        }
    } else if (wid == 1) {
        // ---------------- MMA warp (single elected thread)
        if (elect_one_pred()) {
            int st = 0, it = 0;
            for (int c = 0; c < N_CHUNKS; ++c) {
                MBARRIER_WAIT_PARITY(sbase + OFF_FULL + st * 8, it & 1);
                const uint32_t bb = sbase + st * STAGE_BYTES;
                uint64_t dA = make_desc_sw64(bb + ST_A);
                uint64_t dB = make_desc_sw64(bb + ST_B);
                #pragma unroll
                for (int h = 0; h < 2; ++h) {                 // M halves
                    const uint32_t D   = tmem + h * 256;
                    const uint64_t hof = h * 512;             // 128 rows x 64B = 512 units
                    #pragma unroll
                    for (int kk = 0; kk < 2; ++kk) {          // K=8 steps (+2 units = 32B)
                        mma_tf32_ss(D, dA + hof + kk * 2, dB + kk * 2, MMA_IDESC,
                                    !(c == 0 && kk == 0));
                    }
                }
                TCGEN05_COMMIT(sbase + OFF_EMPTY + st * 8);
                if (++st == NSTAGE) { st = 0; ++it; }
            }
            TCGEN05_COMMIT(sbase + OFF_FINAL);
        }
    }

    // ---------------- epilogue: 8 warps (half = wid>>2, sub = wid&3)
    MBARRIER_WAIT_PARITY(sbase + OFF_FINAL, 0);
    TCGEN05_FENCE_AFTER();

    {
        const int half = wid >> 2, sub = wid & 3;
        const int row  = tile_m + half * 128 + sub * 32 + lid;
        float* outp = H + (size_t)(e * CAP + row) * DIM + tile_n;
        const float* bs = (const float*)(smem + OFF_BIAS);
        const uint32_t dbase = tmem + half * 256;
        #pragma unroll
        for (int base = 0; base < 256; base += 32) {
            uint32_t r[32];
            TCGEN05_LD_X32(r, dbase + base);
            TCGEN05_WAIT_LD();
            float v[32];
            #pragma unroll
            for (int i = 0; i < 32; ++i)
                v[i] = fmaxf(__uint_as_float(r[i]) + bs[base + i], 0.f);
            #pragma unroll
            for (int q = 0; q < 8; ++q)
                *(float4*)(outp + base + q * 4) = *(float4*)&v[q * 4];
        }
        TCGEN05_FENCE_BEFORE();
    }
    __syncthreads();
    if (tid == 0) {
        #pragma unroll
        for (int s = 0; s < NSTAGE; ++s) {
            MBARRIER_INVAL(sbase + OFF_FULL  + s * 8);
            MBARRIER_INVAL(sbase + OFF_EMPTY + s * 8);
        }
        MBARRIER_INVAL(sbase + OFF_FINAL);
    }
    __syncthreads();
    if (wid == 0) TCGEN05_DEALLOC(tmem, 512);

#else
    // ---------------- trivial correct fallback (family-level image; not used on GB300)
    const int e      = blockIdx.z;
    const int tile_n = blockIdx.x * 256;
    const int tile_m = blockIdx.y * 256;
    const int tid    = threadIdx.x;
    const int row    = tile_m + tid;
    const float* Ap = X + (size_t)(e * CAP + row) * DIM;
    for (int n = 0; n < 256; ++n) {
        const float* Bp = Wt + ((size_t)e * DIM + tile_n + n) * DIM;
        float s = 0.f;
        for (int k = 0; k < DIM; ++k) s = fmaf(Ap[k], Bp[k], s);
        s += bias[e * DIM + tile_n + n];
        H[(size_t)(e * CAP + row) * DIM + tile_n + n] = fmaxf(s, 0.f);
    }
#endif
}

// ---------------------------------------------------------------------------
// LayerNorm over D=1024 per row; one 256-thread CTA per token. (R3 version)
// ---------------------------------------------------------------------------
__global__ __launch_bounds__(256)
void layernorm_kernel(const float* __restrict__ H,
                      const float* __restrict__ gamma,
                      const float* __restrict__ beta,
                      float* __restrict__ out)
{
    const int row = blockIdx.x;
    const int e   = row >> 10;
    const int tid = threadIdx.x;

    const float* h = H + (size_t)row * DIM;
    float4 v = *(const float4*)(h + tid * 4);

    float s  = v.x + v.y + v.z + v.w;
    float sq = v.x * v.x + v.y * v.y + v.z * v.z + v.w * v.w;

    #pragma unroll
    for (int off = 16; off > 0; off >>= 1) {
        s  += __shfl_xor_sync(0xffffffffu, s,  off);
        sq += __shfl_xor_sync(0xffffffffu, sq, off);
    }

    __shared__ float red_s[8], red_q[8];
    const int wid = tid >> 5, lid = tid & 31;
    if (lid == 0) { red_s[wid] = s; red_q[wid] = sq; }
    __syncthreads();

    __shared__ float s_mean, s_rstd;
    if (wid == 0) {
        float ts = (lid < 8) ? red_s[lid] : 0.f;
        float tq = (lid < 8) ? red_q[lid] : 0.f;
        #pragma unroll
        for (int off = 4; off > 0; off >>= 1) {
            ts += __shfl_xor_sync(0xffffffffu, ts, off);
            tq += __shfl_xor_sync(0xffffffffu, tq, off);
        }
        if (lid == 0) {
            float mean = ts * (1.f / DIM);
            float var  = tq * (1.f / DIM) - mean * mean;
            s_mean = mean;
            s_rstd = rsqrtf(var + LN_EPS);
        }
    }
    __syncthreads();

    const float mean = s_mean, rstd = s_rstd;
    float4 g  = *(const float4*)(gamma + (size_t)e * DIM + tid * 4);
    float4 bt = *(const float4*)(beta  + (size_t)e * DIM + tid * 4);

    float4 o;
    o.x = (v.x - mean) * rstd * g.x + bt.x;
    o.y = (v.y - mean) * rstd * g.y + bt.y;
    o.z = (v.z - mean) * rstd * g.z + bt.z;
    o.w = (v.w - mean) * rstd * g.w + bt.w;
    *(float4*)(out + (size_t)row * DIM + tid * 4) = o;
}

// ---------------------------------------------------------------------------
typedef CUresult (CUDAAPI *pfn_encode_t)(
    CUtensorMap*, CUtensorMapDataType, cuuint32_t, void*,
    const cuuint64_t*, const cuuint64_t*, const cuuint32_t*, const cuuint32_t*,
    CUtensorMapInterleave, CUtensorMapSwizzle, CUtensorMapL2promotion,
    CUtensorMapFloatOOBfill);

static void encode_map_f32(pfn_encode_t fn, CUtensorMap* tm, void* ptr, int nrows)
{
    cuuint64_t dims[2]    = {(cuuint64_t)DIM, (cuuint64_t)nrows};
    cuuint64_t strides[1] = {(cuuint64_t)(DIM * 4)};   // bytes per row (f32)
    cuuint32_t box[2]     = {16, 256};                 // 64B x 256 rows, SW64
    cuuint32_t estr[2]    = {1, 1};
    fn(tm, CU_TENSOR_MAP_DATA_TYPE_FLOAT32, 2, ptr, dims, strides, box, estr,
       CU_TENSOR_MAP_INTERLEAVE_NONE, CU_TENSOR_MAP_SWIZZLE_64B,
       CU_TENSOR_MAP_L2_PROMOTION_L2_128B, CU_TENSOR_MAP_FLOAT_OOB_FILL_NONE);
}

extern "C" void kernel_launch(void* const* d_in, const int* in_sizes, int n_in,
                              void* d_out, int out_size)
{
    const float* x     = (const float*)d_in[0];
    // d_in[1] = expert_frequency (equal capacities) — unused
    const float* W     = (const float*)d_in[2];
    const float* bias  = (const float*)d_in[3];
    const float* gamma = (const float*)d_in[4];
    const float* beta  = (const float*)d_in[5];
    float*       out   = (float*)d_out;

    float *wt, *h;
    cudaGetSymbolAddress((void**)&wt, g_wt);
    cudaGetSymbolAddress((void**)&h,  g_h);

    static bool init_done = false;
    static CUtensorMap tmX, tmW;
    static const float* x_cached = nullptr;
    if (!init_done || x_cached != x) {
        cudaFuncSetAttribute(gemm_tc_kernel,
                             cudaFuncAttributeMaxDynamicSharedMemorySize, SMEM_SIZE);
        void* p = nullptr;
        cudaDriverEntryPointQueryResult qr;
        if (cudaGetDriverEntryPointByVersion("cuTensorMapEncodeTiled", &p, 12000,
                                             cudaEnableDefault, &qr) != cudaSuccess || !p) {
            cudaGetDriverEntryPoint("cuTensorMapEncodeTiled", &p, cudaEnableDefault, &qr);
        }
        pfn_encode_t fn = (pfn_encode_t)p;
        encode_map_f32(fn, &tmX, (void*)x, NTOK);
        encode_map_f32(fn, &tmW, wt, NEXP * DIM);
        init_done = true;
        x_cached = x;
    }

    transpose_w_kernel<<<dim3(16, 8, NEXP), 256>>>(W, wt);

    dim3 grid(DIM / 256, CAP / 256, NEXP);  // 4 x 4 x 8 = 128 CTAs, 1 wave
    gemm_tc_kernel<<<grid, 256, SMEM_SIZE>>>(tmX, tmW, x, wt, bias, h);

    layernorm_kernel<<<NTOK, 256>>>(h, gamma, beta, out);
}